// round 9
// baseline (speedup 1.0000x reference)
#include <cuda_runtime.h>
#include <cuda_fp16.h>
#include <cstdint>
#include <math_constants.h>

// Shapes (fixed by setup_inputs)
#define B_  32
#define C_  256
#define N_  1024
#define M_  1024

// ---------------------------------------------------------------------------
// Device scratch (allocation-free)
// ---------------------------------------------------------------------------
__device__ float  g_S[(size_t)B_ * N_ * M_];          // 128 MB scores
__device__ __half g_Qs[2][N_ * C_];                   // (Q/16) fp16 limbs [n][c]
__device__ __half g_Ks[2][(size_t)B_ * M_ * C_];      // src fp16 limbs, [b][m][c]
__device__ float2 g_cpart[B_][8][M_];                 // per-n-strip col partials (max,sum)
__device__ float  g_cb[B_ * M_];                      // colmax + log(colsum)
__device__ int    g_idx[B_ * N_];                     // per-row argmax

__device__ __forceinline__ void split2(float v, __half& h, __half& m) {
    h = __float2half(v);
    m = __float2half(v - __half2float(h));
}

// ---------------------------------------------------------------------------
// PTX helpers (sm_80-era: valid on base sm_100 target)
// ---------------------------------------------------------------------------
__device__ __forceinline__ uint32_t smem_u32(const void* p) {
    uint32_t a;
    asm("{ .reg .u64 t; cvta.to.shared.u64 t, %1; cvt.u32.u64 %0, t; }" : "=r"(a) : "l"(p));
    return a;
}
#define CP_ASYNC16(saddr, gaddr) \
    asm volatile("cp.async.cg.shared.global [%0], [%1], 16;" \
                 :: "r"(saddr), "l"(gaddr) : "memory")
#define CP_COMMIT()  asm volatile("cp.async.commit_group;" ::: "memory")
#define CP_WAIT(n)   asm volatile("cp.async.wait_group %0;" :: "n"(n) : "memory")

#define LDMATRIX_X4(r0, r1, r2, r3, addr) \
    asm volatile("ldmatrix.sync.aligned.m8n8.x4.shared.b16 {%0,%1,%2,%3}, [%4];" \
                 : "=r"(r0), "=r"(r1), "=r"(r2), "=r"(r3) : "r"(addr))

__device__ __forceinline__ void mma16816(float* d, const uint32_t* a, const uint32_t* b) {
    asm volatile(
        "mma.sync.aligned.m16n8k16.row.col.f32.f16.f16.f32 "
        "{%0,%1,%2,%3}, {%4,%5,%6,%7}, {%8,%9}, {%0,%1,%2,%3};"
        : "+f"(d[0]), "+f"(d[1]), "+f"(d[2]), "+f"(d[3])
        : "r"(a[0]), "r"(a[1]), "r"(a[2]), "r"(a[3]), "r"(b[0]), "r"(b[1]));
}

// ---------------------------------------------------------------------------
// Kernel 0a: split Q (temperature 1/16 folded in)
// ---------------------------------------------------------------------------
__global__ void split_q_kernel(const float* __restrict__ qw) {
    int i = blockIdx.x * 256 + threadIdx.x;
    float v = qw[i] * 0.0625f;
    __half h, m;
    split2(v, h, m);
    g_Qs[0][i] = h; g_Qs[1][i] = m;
}

// ---------------------------------------------------------------------------
// Kernel 0b: split + transpose src [b][c][m] -> [b][m][c]
// ---------------------------------------------------------------------------
__global__ void split_k_kernel(const float* __restrict__ src) {
    __shared__ float tile[32][33];
    int b = blockIdx.z, c0 = blockIdx.y * 32, m0 = blockIdx.x * 32;
    int t = threadIdx.x, tx = t & 31, ty = t >> 5;
    const float* sp = src + (size_t)b * C_ * M_;
    #pragma unroll
    for (int i = 0; i < 4; i++) {
        int c = c0 + ty + i * 8;
        tile[ty + i * 8][tx] = sp[(size_t)c * M_ + m0 + tx];
    }
    __syncthreads();
    #pragma unroll
    for (int i = 0; i < 4; i++) {
        int m = m0 + ty + i * 8;
        float v = tile[tx][ty + i * 8];
        __half h, mm;
        split2(v, h, mm);
        size_t o = ((size_t)b * M_ + m) * C_ + c0 + tx;
        g_Ks[0][o] = h; g_Ks[1][o] = mm;
    }
}

// ---------------------------------------------------------------------------
// Kernel 1: fp16x3 HMMA GEMM, limbs loaded ONCE per k-chunk. STATIC smem only.
//   S[b][n][m] = sum_c (q[n][c]/16) * src[b][c][m]
//   products: hh = A0*B0, hm = A0*B1, mh = A1*B0 (all into one fp32 acc)
// CTA 128n x 128m, 8 warps (4n x 2m), warp tile 32n x 64m.
// K: 16 chunks of 16; per chunk load A0,A1,B0,B1 (4 x 4KB), double-buffered.
// Smem rows are 32B (2 x 16B units); swizzle: unit ^= (row>>2)&1 (conflict-free).
// Fused epilogue: per-column (over this CTA's 128 n-rows) max + sumexp partials.
// ---------------------------------------------------------------------------
#define KC 16
#define NCHUNK 16
#define TILE_BYTES  (128 * 32)           // 4 KB per tile
#define STAGE_BYTES (4 * TILE_BYTES)     // 16 KB: A0,A1,B0,B1

struct GemmSmem {
    char   stages[2][STAGE_BYTES];       // 32 KB
    float2 cstats[4][128];               // 4 KB
};

__device__ __forceinline__ uint32_t sw_addr(uint32_t base, int row, int unit) {
    return base + row * 32 + ((unit ^ ((row >> 2) & 1)) << 4);
}

__global__ __launch_bounds__(256)
void gemm_fp16x3_kernel() {
    __shared__ GemmSmem sm;
    const uint32_t sb0 = smem_u32(sm.stages[0]);

    int tid = threadIdx.x;
    int wid = tid >> 5, lid = tid & 31;
    int wn = wid >> 1, wm = wid & 1;            // 4 x 2 warp grid

    int m0 = blockIdx.x * 128;
    int n0 = blockIdx.y * 128;
    int b  = blockIdx.z;

    const __half* gsrc[4] = {
        g_Qs[0] + (size_t)n0 * C_,                  // A0
        g_Qs[1] + (size_t)n0 * C_,                  // A1
        g_Ks[0] + ((size_t)b * M_ + m0) * C_,       // B0
        g_Ks[1] + ((size_t)b * M_ + m0) * C_        // B1
    };

    // Loader: 4 tiles x 256 16B-units = 1024 units; 4 per thread.
    auto load_chunk = [&](int buf, int kc) {
        uint32_t sbase = sb0 + buf * STAGE_BYTES;
        #pragma unroll
        for (int t = 0; t < 4; t++) {
            int idx  = tid + t * 256;               // 0..1023
            int tile = idx >> 8;                    // 0..3
            int row  = (idx >> 1) & 127;
            int u    = idx & 1;
            CP_ASYNC16(sw_addr(sbase + tile * TILE_BYTES, row, u),
                       gsrc[tile] + (size_t)row * C_ + kc + u * 8);
        }
        CP_COMMIT();
    };

    float acc[2][8][4];
    #pragma unroll
    for (int i = 0; i < 2; i++)
        #pragma unroll
        for (int j = 0; j < 8; j++)
            #pragma unroll
            for (int c = 0; c < 4; c++) acc[i][j][c] = 0.0f;

    load_chunk(0, 0);

    for (int it = 0; it < NCHUNK; it++) {
        __syncthreads();                        // buffer (it+1)&1 free to overwrite
        if (it + 1 < NCHUNK) {
            load_chunk((it + 1) & 1, (it + 1) * KC);
            CP_WAIT(1);
        } else {
            CP_WAIT(0);
        }
        __syncthreads();                        // chunk `it` visible to all

        uint32_t A0b = sb0 + (it & 1) * STAGE_BYTES;
        uint32_t A1b = A0b + TILE_BYTES;
        uint32_t B0b = A0b + 2 * TILE_BYTES;
        uint32_t B1b = A0b + 3 * TILE_BYTES;
        int tile = lid >> 3, trow = lid & 7;

        // A fragments: 2 m16 tiles per limb (k = full 16 of this chunk)
        uint32_t a0F[2][4], a1F[2][4];
        #pragma unroll
        for (int i = 0; i < 2; i++) {
            int row  = wn * 32 + i * 16 + (tile & 1) * 8 + trow;
            int unit = tile >> 1;
            LDMATRIX_X4(a0F[i][0], a0F[i][1], a0F[i][2], a0F[i][3],
                        sw_addr(A0b, row, unit));
            LDMATRIX_X4(a1F[i][0], a1F[i][1], a1F[i][2], a1F[i][3],
                        sw_addr(A1b, row, unit));
        }
        // B fragments: 8 n8 tiles per limb
        uint32_t b0F[8][2], b1F[8][2];
        #pragma unroll
        for (int p = 0; p < 4; p++) {
            int row  = wm * 64 + p * 16 + (tile >> 1) * 8 + trow;
            int unit = tile & 1;
            uint32_t r0, r1, r2, r3;
            LDMATRIX_X4(r0, r1, r2, r3, sw_addr(B0b, row, unit));
            b0F[2 * p][0] = r0;     b0F[2 * p][1] = r1;
            b0F[2 * p + 1][0] = r2; b0F[2 * p + 1][1] = r3;
            LDMATRIX_X4(r0, r1, r2, r3, sw_addr(B1b, row, unit));
            b1F[2 * p][0] = r0;     b1F[2 * p][1] = r1;
            b1F[2 * p + 1][0] = r2; b1F[2 * p + 1][1] = r3;
        }
        #pragma unroll
        for (int i = 0; i < 2; i++)
            #pragma unroll
            for (int j = 0; j < 8; j++) {
                mma16816(acc[i][j], a0F[i], b0F[j]);   // hh
                mma16816(acc[i][j], a0F[i], b1F[j]);   // hm
                mma16816(acc[i][j], a1F[i], b0F[j]);   // mh
            }
    }

    // ---- Epilogue 1: write S ----
    // fragment layout: d0,d1 @ (r_in, c_in..+1); d2,d3 @ (r_in+8, c_in..+1)
    int r_in = lid >> 2, c_in = (lid & 3) * 2;
    #pragma unroll
    for (int i = 0; i < 2; i++) {
        #pragma unroll
        for (int j = 0; j < 8; j++) {
            int gr = n0 + wn * 32 + i * 16 + r_in;
            int gc = m0 + wm * 64 + j * 8 + c_in;
            float* p0 = g_S + ((size_t)b * N_ + gr) * M_ + gc;
            float* p1 = p0 + 8 * M_;
            *(float2*)p0 = make_float2(acc[i][j][0], acc[i][j][1]);
            *(float2*)p1 = make_float2(acc[i][j][2], acc[i][j][3]);
        }
    }

    // ---- Epilogue 2: column (over n) max + sumexp partials ----
    #pragma unroll
    for (int j = 0; j < 8; j++) {
        #pragma unroll
        for (int o = 0; o < 2; o++) {
            float v0 = acc[0][j][o], v1 = acc[0][j][o + 2];
            float v2 = acc[1][j][o], v3 = acc[1][j][o + 2];
            float mx = fmaxf(fmaxf(v0, v1), fmaxf(v2, v3));
            #pragma unroll
            for (int off = 4; off <= 16; off <<= 1)
                mx = fmaxf(mx, __shfl_xor_sync(0xffffffffu, mx, off));
            float sum = __expf(v0 - mx) + __expf(v1 - mx)
                      + __expf(v2 - mx) + __expf(v3 - mx);
            #pragma unroll
            for (int off = 4; off <= 16; off <<= 1)
                sum += __shfl_xor_sync(0xffffffffu, sum, off);
            if (lid < 4)
                sm.cstats[wn][wm * 64 + j * 8 + lid * 2 + o] = make_float2(mx, sum);
        }
    }
    __syncthreads();
    if (tid < 128) {
        float gm = -CUDART_INF_F, gs = 0.0f;
        #pragma unroll
        for (int w = 0; w < 4; w++) {
            float2 p = sm.cstats[w][tid];
            if (p.x > gm) { gs = gs * __expf(gm - p.x) + p.y; gm = p.x; }
            else          { gs += p.y * __expf(p.x - gm); }
        }
        g_cpart[b][blockIdx.y][m0 + tid] = make_float2(gm, gs);
    }
}

// ---------------------------------------------------------------------------
// Kernel 2: combine 8 n-strip partials -> cb[b][m] = colmax + log(colsum)
// ---------------------------------------------------------------------------
__global__ void reduce_cb_kernel() {
    int b = blockIdx.y;
    int m = blockIdx.x * 256 + threadIdx.x;
    float gm = -CUDART_INF_F, gs = 0.0f;
    #pragma unroll
    for (int s = 0; s < 8; s++) {
        float2 p = g_cpart[b][s][m];
        if (p.x > gm) { gs = gs * __expf(gm - p.x) + p.y; gm = p.x; }
        else          { gs += p.y * __expf(p.x - gm); }
    }
    g_cb[b * M_ + m] = gm + logf(gs);
}

// ---------------------------------------------------------------------------
// Kernel 3: per-row argmax of  L = 2*S - cb.  One warp per row, float4 loads.
// ---------------------------------------------------------------------------
__global__ void rowargmax_kernel() {
    int row  = blockIdx.x * 8 + (threadIdx.x >> 5);
    int lane = threadIdx.x & 31;
    int b    = row >> 10;
    const float4* Sp = (const float4*)(g_S + (size_t)row * M_);
    const float4* cb = (const float4*)(g_cb + b * M_);

    float best = -CUDART_INF_F; int bi = 0;
    #pragma unroll 2
    for (int q = lane; q < M_ / 4; q += 32) {
        float4 s = Sp[q];
        float4 c = cb[q];
        int m = q * 4;
        float L0 = 2.0f * s.x - c.x;
        float L1 = 2.0f * s.y - c.y;
        float L2 = 2.0f * s.z - c.z;
        float L3 = 2.0f * s.w - c.w;
        if (L0 > best) { best = L0; bi = m; }
        if (L1 > best) { best = L1; bi = m + 1; }
        if (L2 > best) { best = L2; bi = m + 2; }
        if (L3 > best) { best = L3; bi = m + 3; }
    }
    #pragma unroll
    for (int off = 16; off > 0; off >>= 1) {
        float ob = __shfl_down_sync(0xffffffffu, best, off);
        int   oi = __shfl_down_sync(0xffffffffu, bi, off);
        if (ob > best || (ob == best && oi < bi)) { best = ob; bi = oi; }
    }
    if (lane == 0) g_idx[row] = bi;
}

// ---------------------------------------------------------------------------
// Kernel 4: gather.  out[b][c][n] = src[b][c][ idx[b][n] ]
// ---------------------------------------------------------------------------
__global__ void gather_kernel(const float* __restrict__ src, float* __restrict__ out) {
    __shared__ float row[M_];
    __shared__ int   sidx[N_];
    int b = blockIdx.y, c = blockIdx.x;
    const float* sr = src + ((size_t)b * C_ + c) * M_;
    const int*   ip = g_idx + b * N_;
    float*       op = out + ((size_t)b * C_ + c) * N_;
    int t = threadIdx.x;
    for (int i = t; i < M_; i += blockDim.x) { row[i] = sr[i]; sidx[i] = ip[i]; }
    __syncthreads();
    for (int i = t; i < N_; i += blockDim.x) op[i] = row[sidx[i]];
}

// ---------------------------------------------------------------------------
extern "C" void kernel_launch(void* const* d_in, const int* in_sizes, int n_in,
                              void* d_out, int out_size) {
    const float* src = (const float*)d_in[0];   // [32,256,32,32]
    const float* qw  = (const float*)d_in[1];   // [1024,256]
    float* out = (float*)d_out;
    (void)in_sizes; (void)n_in; (void)out_size;

    split_q_kernel<<<N_ * C_ / 256, 256>>>(qw);
    split_k_kernel<<<dim3(M_ / 32, C_ / 32, B_), 256>>>(src);

    gemm_fp16x3_kernel<<<dim3(M_ / 128, N_ / 128, B_), 256>>>();

    reduce_cb_kernel<<<dim3(M_ / 256, B_), 256>>>();
    rowargmax_kernel<<<(B_ * N_) / 8, 256>>>();
    gather_kernel<<<dim3(C_, B_), 256>>>(src, out);
}